// round 13
// baseline (speedup 1.0000x reference)
#include <cuda_runtime.h>
#include <cuda_fp16.h>
#include <cstdint>
#include <math.h>

// Shapes
#define BSZ   2048
#define IN    128
#define ON    128
#define DN    2
#define NN    256            // O*D
#define SPLIT 8
#define IPS   (IN / SPLIT)   // 16 i's per k-slice
#define NCOMB 256

// Scratch (static device arrays -- no allocation)
__device__ float g_part[SPLIT][BSZ][NN];       // 16 MB split-K partials
__device__ float g_sbsum[NN];
__device__ float g_bstat[NCOMB][4];
__device__ unsigned int g_ctr;
__device__ __half g_w[IN * NN * 64];           // 4 MB, [i][n=(o,x)][k=(u,v)]
__device__ __half g_s[SPLIT * NN * 64];        // silu-branch B per slice

// ---------------------------------------------------------------------------
// PTX helpers (sm_80-class ISA only: ldmatrix / mma.sync / cp.async)
// ---------------------------------------------------------------------------
__device__ __forceinline__ uint32_t smem_u32(const void* p) {
    uint32_t a;
    asm("{ .reg .u64 t; cvta.to.shared.u64 t, %1; cvt.u32.u64 %0, t; }" : "=r"(a) : "l"(p));
    return a;
}
__device__ __forceinline__ void ldsm_x4(uint32_t* r, uint32_t addr) {
    asm volatile("ldmatrix.sync.aligned.m8n8.x4.shared.b16 {%0,%1,%2,%3}, [%4];"
                 : "=r"(r[0]), "=r"(r[1]), "=r"(r[2]), "=r"(r[3]) : "r"(addr));
}
__device__ __forceinline__ void mma_f16(float* c, const uint32_t* a, const uint32_t* b) {
    asm volatile(
        "mma.sync.aligned.m16n8k16.row.col.f32.f16.f16.f32 "
        "{%0,%1,%2,%3}, {%4,%5,%6,%7}, {%8,%9}, {%0,%1,%2,%3};"
        : "+f"(c[0]), "+f"(c[1]), "+f"(c[2]), "+f"(c[3])
        : "r"(a[0]), "r"(a[1]), "r"(a[2]), "r"(a[3]), "r"(b[0]), "r"(b[1]));
}
#define CP_ASYNC16(dst, src) asm volatile("cp.async.cg.shared.global [%0], [%1], 16;" :: "r"(dst), "l"(src) : "memory")
#define CP_COMMIT()          asm volatile("cp.async.commit_group;" ::: "memory")
#define CP_WAIT(n)           asm volatile("cp.async.wait_group %0;" :: "n"(n) : "memory")

__device__ __forceinline__ uint32_t pack_h2(float a, float b) {
    __half2 h = __floats2half2_rn(a, b);
    return *(uint32_t*)&h;
}

// smem geometry: B rows padded to 72 fp16 (144 B); 128 rows x 64 k per matrix
#define RPAD   72
#define MAT    (128 * RPAD * 2)            // 18432 B
#define STG    (2 * MAT)                   // one pipeline stage = 2 i's
#define SMEM_TC (3 * STG)                  // 110592 B -> 2 CTAs/SM

// ---------------------------------------------------------------------------
// Prep: weights -> fp16 in layout [i][n=(o*2+x)][k=(u*8+v)]. Also resets g_ctr.
// ---------------------------------------------------------------------------
__global__ void k_prep(const float* __restrict__ w) {
    if (blockIdx.x == 0 && threadIdx.x == 0) g_ctr = 0;
    int idx4 = blockIdx.x * 256 + threadIdx.x;   // 0 .. 524287
    int flat = idx4 * 4;
    int i  = flat >> 14;
    int o  = (flat >> 7) & 127;
    int u  = (flat >> 4) & 7;
    int v0 = (flat >> 1) & 7;
    float4 w4 = *(const float4*)(w + flat);       // (v0,x0)(v0,x1)(v1,x0)(v1,x1)

    int k0 = u * 8 + v0;
    size_t r0 = ((size_t)i * NN + o * 2)     * 64 + k0;
    size_t r1 = ((size_t)i * NN + o * 2 + 1) * 64 + k0;

    *(__half2*)(g_w + r0) = __half2(__float2half_rn(w4.x), __float2half_rn(w4.z));
    *(__half2*)(g_w + r1) = __half2(__float2half_rn(w4.y), __float2half_rn(w4.w));
}

// ---------------------------------------------------------------------------
// Prep2: silu-branch B per slice (k<32 valid, zero-pad to 64). Block 512: sbsum.
// ---------------------------------------------------------------------------
__global__ void k_prep2(const float* __restrict__ sw, const float* __restrict__ sb,
                        const float* __restrict__ cay) {
    if (blockIdx.x == 512) {
        int n = threadIdx.x;
        float s = 0.f;
        for (int i = 0; i < IN; i++) s += sb[i * NN + n];
        g_sbsum[n] = s;
        return;
    }
    int idx = blockIdx.x * 256 + threadIdx.x;    // 0 .. 131071
    int s = idx >> 14;
    int n = (idx >> 6) & 255;
    int k = idx & 63;
    float val = 0.f;
    if (k < 32) {
        int ii = k >> 1, y = k & 1, o = n >> 1, z = n & 1;
        int i = s * IPS + ii;
        float sw0 = sw[((size_t)i * ON + o) * 2 + 0];
        float sw1 = sw[((size_t)i * ON + o) * 2 + 1];
        val = sw0 * cay[y * 2 + z] + sw1 * cay[4 + y * 2 + z];
    }
    g_s[idx] = __float2half_rn(val);
}

// nop for ncu slot alignment (k_tc stays at launch position 4)
__global__ void k_nop() {}

// ---------------------------------------------------------------------------
// Register A-frag builders (same as R11).
// ---------------------------------------------------------------------------
__device__ __forceinline__ void build_A_rbf(uint32_t ph[4][8],
                                            const float* xp_own, int i,
                                            const float* gS, const float* sKu,
                                            int lid, int q) {
    float xr = xp_own[i * 2], xi = xp_own[i * 2 + 1];
    int lbase = lid & 28;
    float xiq[4];
#pragma unroll
    for (int qp = 0; qp < 4; qp++)
        xiq[qp] = __shfl_sync(0xffffffffu, xi, lbase | qp);

    float eu[8];
    {
        float d0 = xr - gS[0];
        float delta = gS[1] - gS[0];
        float e0 = __expf(-d0 * d0);
        float s  = __expf(2.f * delta * d0);
        eu[0] = e0;
        float sp = s;
#pragma unroll
        for (int u = 1; u < 8; u++) {
            eu[u] = e0 * sp * sKu[u];
            sp *= s;
        }
    }
    float gv0 = gS[8 + 2 * q], gv1 = gS[8 + 2 * q + 1];
    float ev0[4], ev1[4];
#pragma unroll
    for (int qp = 0; qp < 4; qp++) {
        float d0 = xiq[qp] - gv0; ev0[qp] = __expf(-d0 * d0);
        float d1 = xiq[qp] - gv1; ev1[qp] = __expf(-d1 * d1);
    }
#pragma unroll
    for (int qp = 0; qp < 4; qp++) {
#pragma unroll
        for (int u = 0; u < 8; u++) {
            float es = __shfl_sync(0xffffffffu, eu[u], lbase | qp);
            ph[qp][u] = pack_h2(es * ev0[qp], es * ev1[qp]);
        }
    }
}

__device__ __forceinline__ void build_A_silu(uint32_t ph[4][8],
                                             const float* x, int row_base,
                                             int i0, int gr, int q) {
#pragma unroll
    for (int qp = 0; qp < 4; qp++) {
        const float* xq = x + (size_t)(row_base + qp * 8 + gr) * (IN * DN) + i0 * 2;
#pragma unroll
        for (int ks = 0; ks < 2; ks++) {
            float2 p0 = *(const float2*)(xq + ks * 16 + 2 * q);
            float2 p1 = *(const float2*)(xq + ks * 16 + 8 + 2 * q);
            float s00 = p0.x / (1.f + __expf(-p0.x));
            float s01 = p0.y / (1.f + __expf(-p0.y));
            float s10 = p1.x / (1.f + __expf(-p1.x));
            float s11 = p1.y / (1.f + __expf(-p1.y));
            ph[qp][2 * ks]     = pack_h2(s00, s01);
            ph[qp][2 * ks + 1] = pack_h2(s10, s11);
        }
#pragma unroll
        for (int u = 4; u < 8; u++) ph[qp][u] = 0u;
    }
}

// ---------------------------------------------------------------------------
// Tensor-core split-K GEMM via mma.sync (fp16 single-pass), A IN REGISTERS.
// B pipeline: 3 stages x (2 i's per stage) -> only 9 sync points per CTA.
// grid (16, 2, SPLIT) = 256 CTAs, 2 CTAs/SM. CTA 128x128, warp tile 32x64.
// ---------------------------------------------------------------------------
__global__ __launch_bounds__(256, 2)
void k_tc(const float* __restrict__ x, const float* __restrict__ grd) {
    extern __shared__ char smdyn[];
    __shared__ float gS[16];
    __shared__ float sKu[8];

    const int tid = threadIdx.x;
    const int wid = tid >> 5, lid = tid & 31;
    const int bm = blockIdx.x * 128;
    const int n0 = blockIdx.y * 128;
    const int sl = blockIdx.z;
    const int i0 = sl * IPS;

    const uint32_t sbase = smem_u32(smdyn);
    const int wm = wid >> 1, wn = wid & 1;
    const int R = wm * 32, C = wn * 64;
    const int gr = lid >> 2, q = lid & 3;
    const int r_own = R + q * 8 + gr;
    const float* xp_own = x + (size_t)(bm + r_own) * (IN * DN);

    float acc[2][8][4];
#pragma unroll
    for (int t = 0; t < 2; t++)
#pragma unroll
        for (int j = 0; j < 8; j++)
#pragma unroll
            for (int e = 0; e < 4; e++) acc[t][j][e] = 0.f;

    // stage st < 8: 2 i's (2048 chunks) from g_w (sub_ selects the i!);
    // st == 8: silu (1024 chunks)
#define ISSUE_STAGE(st_)                                                         \
    do {                                                                         \
        uint32_t nb_ = sbase + (uint32_t)((st_) % 3) * STG;                      \
        if ((st_) < 8) {                                                         \
            const __half* sH_ = g_w + ((size_t)(i0 + 2 * (st_)) * NN + n0) * 64; \
            _Pragma("unroll")                                                    \
            for (int c_ = 0; c_ < 8; c_++) {                                     \
                int ch_ = tid + c_ * 256;                                        \
                int c2_ = ch_ & 1023, sub_ = ch_ >> 10;                          \
                uint32_t dst_ = (uint32_t)(sub_ * MAT                            \
                    + (c2_ >> 3) * (RPAD * 2) + (c2_ & 7) * 16);                 \
                CP_ASYNC16(nb_ + dst_,                                           \
                           sH_ + (size_t)sub_ * (NN * 64) + c2_ * 8);            \
            }                                                                    \
        } else {                                                                 \
            const __half* sH_ = g_s + ((size_t)sl * NN + n0) * 64;               \
            _Pragma("unroll")                                                    \
            for (int c_ = 0; c_ < 4; c_++) {                                     \
                int ch_ = tid + c_ * 256;                                        \
                uint32_t dst_ = (uint32_t)((ch_ >> 3) * (RPAD * 2)               \
                    + (ch_ & 7) * 16);                                           \
                CP_ASYNC16(nb_ + dst_, sH_ + ch_ * 8);                           \
            }                                                                    \
        }                                                                        \
        CP_COMMIT();                                                             \
    } while (0)

    // ---- preamble: issue stages 0,1; init gS + Ku ----
    ISSUE_STAGE(0);
    ISSUE_STAGE(1);
    if (tid < 8) {
        gS[tid]     = grd[tid * 16];       // g[u] (real axis)
        gS[8 + tid] = grd[tid * 2 + 1];    // g[v] (imag axis)
    }
    __syncthreads();
    if (tid < 8) {
        float du = gS[tid] - gS[0];
        sKu[tid] = __expf(-du * du);
    }
    __syncthreads();

    uint32_t ph[4][8];
    build_A_rbf(ph, xp_own, i0, gS, sKu, lid, q);

    int slot = 0;   // global i-slot 0..16 (16 = silu)
    for (int st = 0; st <= 8; st++) {
        if (st < 8) CP_WAIT(1);
        else        CP_WAIT(0);
        __syncthreads();               // stage st visible; stage (st+2)%3 reads done

        if (st + 2 <= 8) ISSUE_STAGE(st + 2);

        const int nsub = (st == 8) ? 1 : 2;
        for (int sub = 0; sub < nsub; sub++) {
            const uint32_t bufB = sbase + (uint32_t)(st % 3) * STG
                                        + (uint32_t)sub * MAT;
            // ---- MMA over K=64 for this slot ----
#pragma unroll
            for (int ks = 0; ks < 4; ks++) {
                uint32_t a0[4] = { ph[0][2 * ks], ph[1][2 * ks],
                                   ph[0][2 * ks + 1], ph[1][2 * ks + 1] };
                uint32_t a1[4] = { ph[2][2 * ks], ph[3][2 * ks],
                                   ph[2][2 * ks + 1], ph[3][2 * ks + 1] };
#pragma unroll
                for (int jj = 0; jj < 4; jj++) {
                    int nrow = C + jj * 16 + ((lid >> 4) * 8) + (lid & 7);
                    uint32_t cb = (uint32_t)(ks * 32 + ((lid >> 3) & 1) * 16);
                    uint32_t bh[4];
                    ldsm_x4(bh, bufB + (uint32_t)(nrow * (RPAD * 2)) + cb);
                    mma_f16(acc[0][jj * 2],     a0, bh);
                    mma_f16(acc[0][jj * 2 + 1], a0, bh + 2);
                    mma_f16(acc[1][jj * 2],     a1, bh);
                    mma_f16(acc[1][jj * 2 + 1], a1, bh + 2);
                }
            }
            // ---- build A-frags for next slot (overlaps HMMA drain) ----
            int next = slot + 1;
            if (next < IPS)
                build_A_rbf(ph, xp_own, i0 + next, gS, sKu, lid, q);
            else if (next == IPS)
                build_A_silu(ph, x + (size_t)bm * (IN * DN), R, i0, gr, q);
            slot++;
        }
    }
#undef ISSUE_STAGE

    // ---- epilogue: registers -> split-K partials ----
#pragma unroll
    for (int t = 0; t < 2; t++) {
#pragma unroll
        for (int j = 0; j < 8; j++) {
            int row = bm + R + t * 16 + (lid >> 2);
            int col = n0 + C + j * 8 + (lid & 3) * 2;
            *(float2*)&g_part[sl][row][col]     = make_float2(acc[t][j][0], acc[t][j][1]);
            *(float2*)&g_part[sl][row + 8][col] = make_float2(acc[t][j][2], acc[t][j][3]);
        }
    }
}

// ---------------------------------------------------------------------------
// Combine + BN + normalize in ONE kernel, with a grid-wide spin barrier.
// grid 256 x 256; all CTAs co-resident (tiny footprint) -> barrier is safe.
// v values stay in registers across the barrier; g_pre eliminated.
// ---------------------------------------------------------------------------
__global__ __launch_bounds__(256)
void k_combine(const float* __restrict__ gamma, const float* __restrict__ beta,
               float* __restrict__ out) {
    __shared__ float rs[256], rq[256], rs1[256], rq1[256];
    __shared__ float st4[4];
    const int tid = threadIdx.x;
    const int i0 = blockIdx.x * 512 + tid;     // float4 ids i0, i0+256

    float4 v0 = ((const float4*)g_sbsum)[i0 & 63];
    float4 v1 = ((const float4*)g_sbsum)[(i0 + 256) & 63];
    const float4* pp = (const float4*)g_part;
#pragma unroll
    for (int s = 0; s < SPLIT; s++) {
        float4 p0 = pp[(size_t)s * 131072 + i0];
        float4 p1 = pp[(size_t)s * 131072 + i0 + 256];
        v0.x += p0.x; v0.y += p0.y; v0.z += p0.z; v0.w += p0.w;
        v1.x += p1.x; v1.y += p1.y; v1.z += p1.z; v1.w += p1.w;
    }

    rs[tid]  = v0.x + v0.z + v1.x + v1.z;
    rs1[tid] = v0.y + v0.w + v1.y + v1.w;
    rq[tid]  = v0.x * v0.x + v0.z * v0.z + v1.x * v1.x + v1.z * v1.z;
    rq1[tid] = v0.y * v0.y + v0.w * v0.w + v1.y * v1.y + v1.w * v1.w;
    __syncthreads();
    for (int s = 128; s >= 1; s >>= 1) {
        if (tid < s) {
            rs[tid] += rs[tid + s];  rs1[tid] += rs1[tid + s];
            rq[tid] += rq[tid + s];  rq1[tid] += rq1[tid + s];
        }
        __syncthreads();
    }
    if (tid == 0) {
        g_bstat[blockIdx.x][0] = rs[0];
        g_bstat[blockIdx.x][1] = rs1[0];
        g_bstat[blockIdx.x][2] = rq[0];
        g_bstat[blockIdx.x][3] = rq1[0];
        __threadfence();
        atomicAdd(&g_ctr, 1u);
        while (atomicAdd(&g_ctr, 0u) < (unsigned)gridDim.x) { }
        __threadfence();
    }
    __syncthreads();

    // every CTA redundantly reduces bstat -> stats
    rs[tid]  = g_bstat[tid][0];
    rs1[tid] = g_bstat[tid][1];
    rq[tid]  = g_bstat[tid][2];
    rq1[tid] = g_bstat[tid][3];
    __syncthreads();
    for (int s = 128; s >= 1; s >>= 1) {
        if (tid < s) {
            rs[tid] += rs[tid + s];  rs1[tid] += rs1[tid + s];
            rq[tid] += rq[tid + s];  rq1[tid] += rq1[tid + s];
        }
        __syncthreads();
    }
    if (tid == 0) {
        const float Ninv = 1.f / (2048.f * 128.f);
        float m0 = rs[0] * Ninv, m1 = rs1[0] * Ninv;
        float va0 = rq[0] * Ninv - m0 * m0;
        float va1 = rq1[0] * Ninv - m1 * m1;
        float sc0 = gamma[0] * rsqrtf(va0 + 1e-5f);
        float sc1 = gamma[1] * rsqrtf(va1 + 1e-5f);
        st4[0] = sc0; st4[1] = sc1;
        st4[2] = beta[0] - m0 * sc0;
        st4[3] = beta[1] - m1 * sc1;
    }
    __syncthreads();

    float s0 = st4[0], s1 = st4[1], h0 = st4[2], h1 = st4[3];
    v0.x = v0.x * s0 + h0;  v0.y = v0.y * s1 + h1;
    v0.z = v0.z * s0 + h0;  v0.w = v0.w * s1 + h1;
    v1.x = v1.x * s0 + h0;  v1.y = v1.y * s1 + h1;
    v1.z = v1.z * s0 + h0;  v1.w = v1.w * s1 + h1;
    ((float4*)out)[i0]       = v0;
    ((float4*)out)[i0 + 256] = v1;
}

// ---------------------------------------------------------------------------
extern "C" void kernel_launch(void* const* d_in, const int* in_sizes, int n_in,
                              void* d_out, int out_size) {
    const float* x     = (const float*)d_in[0];
    const float* w     = (const float*)d_in[1];
    const float* sw    = (const float*)d_in[2];
    const float* sb    = (const float*)d_in[3];
    const float* gamma = (const float*)d_in[4];
    const float* beta  = (const float*)d_in[5];
    const float* grd   = (const float*)d_in[6];
    const float* cay   = (const float*)d_in[7];
    float* out = (float*)d_out;

    static int once = 0;
    if (!once) {
        cudaFuncSetAttribute(k_tc, cudaFuncAttributeMaxDynamicSharedMemorySize, SMEM_TC);
        once = 1;
    }

    k_prep<<<2048, 256>>>(w);               // 1 (also resets g_ctr)
    k_prep2<<<513, 256>>>(sw, sb, cay);     // 2
    k_nop<<<1, 32>>>();                     // 3 (slot alignment)
    k_tc<<<dim3(16, 2, SPLIT), 256, SMEM_TC>>>(x, grd);  // 4 <- profiled
    k_combine<<<NCOMB, 256>>>(gamma, beta, out);         // 5
}

// round 14
// speedup vs baseline: 1.2851x; 1.2851x over previous
#include <cuda_runtime.h>
#include <cuda_fp16.h>
#include <cstdint>
#include <math.h>

// Shapes
#define BSZ   2048
#define IN    128
#define ON    128
#define DN    2
#define NN    256            // O*D
#define SPLIT 8
#define IPS   (IN / SPLIT)   // 16 i's per k-slice
#define NCOMB 128

// Scratch (static device arrays -- no allocation)
__device__ float g_part[SPLIT][BSZ][NN];       // 16 MB split-K partials
__device__ float g_pre[BSZ][NN];
__device__ float g_sbsum[NN];
__device__ float g_bstat[NCOMB][4];
__device__ __half g_w[IN * NN * 64];           // 4 MB, [i][n=(o,x)][k=(u,v)]
__device__ __half g_s[SPLIT * NN * 64];        // silu-branch B per slice

// ---------------------------------------------------------------------------
// PTX helpers (sm_80-class ISA only: ldmatrix / mma.sync / cp.async)
// ---------------------------------------------------------------------------
__device__ __forceinline__ uint32_t smem_u32(const void* p) {
    uint32_t a;
    asm("{ .reg .u64 t; cvta.to.shared.u64 t, %1; cvt.u32.u64 %0, t; }" : "=r"(a) : "l"(p));
    return a;
}
__device__ __forceinline__ void ldsm_x4(uint32_t* r, uint32_t addr) {
    asm volatile("ldmatrix.sync.aligned.m8n8.x4.shared.b16 {%0,%1,%2,%3}, [%4];"
                 : "=r"(r[0]), "=r"(r[1]), "=r"(r[2]), "=r"(r[3]) : "r"(addr));
}
__device__ __forceinline__ void mma_f16(float* c, const uint32_t* a, const uint32_t* b) {
    asm volatile(
        "mma.sync.aligned.m16n8k16.row.col.f32.f16.f16.f32 "
        "{%0,%1,%2,%3}, {%4,%5,%6,%7}, {%8,%9}, {%0,%1,%2,%3};"
        : "+f"(c[0]), "+f"(c[1]), "+f"(c[2]), "+f"(c[3])
        : "r"(a[0]), "r"(a[1]), "r"(a[2]), "r"(a[3]), "r"(b[0]), "r"(b[1]));
}
#define CP_ASYNC16(dst, src) asm volatile("cp.async.cg.shared.global [%0], [%1], 16;" :: "r"(dst), "l"(src) : "memory")
#define CP_COMMIT()          asm volatile("cp.async.commit_group;" ::: "memory")
#define CP_WAIT(n)           asm volatile("cp.async.wait_group %0;" :: "n"(n) : "memory")

__device__ __forceinline__ uint32_t pack_h2(float a, float b) {
    __half2 h = __floats2half2_rn(a, b);
    return *(uint32_t*)&h;
}

// smem geometry: B rows padded to 72 fp16 (144 B); 128 rows x 64 k per stage
#define RPAD   72
#define MAT    (128 * RPAD * 2)            // 18432 B
#define B_OFF(p)  ((uint32_t)(p) * MAT)
#define SMEM_TC   (3 * MAT)                // 55296 B -> 2 CTAs/SM

// ---------------------------------------------------------------------------
// Merged prep:
//   blocks [0, 2048):    weights -> fp16 g_w in [i][n=(o*2+x)][k=(u*8+v)]
//   blocks [2048, 2560): silu-branch B -> g_s (k<32 valid, zero-pad to 64)
//   block  2560:         sbsum
// ---------------------------------------------------------------------------
__global__ void k_prep(const float* __restrict__ w, const float* __restrict__ sw,
                       const float* __restrict__ sb, const float* __restrict__ cay) {
    int blk = blockIdx.x;
    if (blk < 2048) {
        int idx4 = blk * 256 + threadIdx.x;
        int flat = idx4 * 4;
        int i  = flat >> 14;
        int o  = (flat >> 7) & 127;
        int u  = (flat >> 4) & 7;
        int v0 = (flat >> 1) & 7;
        float4 w4 = *(const float4*)(w + flat);   // (v0,x0)(v0,x1)(v1,x0)(v1,x1)
        int k0 = u * 8 + v0;
        size_t r0 = ((size_t)i * NN + o * 2)     * 64 + k0;
        size_t r1 = ((size_t)i * NN + o * 2 + 1) * 64 + k0;
        *(__half2*)(g_w + r0) = __half2(__float2half_rn(w4.x), __float2half_rn(w4.z));
        *(__half2*)(g_w + r1) = __half2(__float2half_rn(w4.y), __float2half_rn(w4.w));
    } else if (blk < 2560) {
        int idx = (blk - 2048) * 256 + threadIdx.x;    // 0 .. 131071
        int s = idx >> 14;
        int n = (idx >> 6) & 255;
        int k = idx & 63;
        float val = 0.f;
        if (k < 32) {
            int ii = k >> 1, y = k & 1, o = n >> 1, z = n & 1;
            int i = s * IPS + ii;
            float sw0 = sw[((size_t)i * ON + o) * 2 + 0];
            float sw1 = sw[((size_t)i * ON + o) * 2 + 1];
            val = sw0 * cay[y * 2 + z] + sw1 * cay[4 + y * 2 + z];
        }
        g_s[idx] = __float2half_rn(val);
    } else {
        int n = threadIdx.x;
        float s = 0.f;
        for (int i = 0; i < IN; i++) s += sb[i * NN + n];
        g_sbsum[n] = s;
    }
}

// ---------------------------------------------------------------------------
// Register A-frag builders (R11-proven).
// ---------------------------------------------------------------------------
__device__ __forceinline__ void build_A_rbf(uint32_t ph[4][8],
                                            const float* xp_own, int i,
                                            const float* gS, const float* sKu,
                                            int lid, int q) {
    float xr = xp_own[i * 2], xi = xp_own[i * 2 + 1];
    int lbase = lid & 28;
    float xiq[4];
#pragma unroll
    for (int qp = 0; qp < 4; qp++)
        xiq[qp] = __shfl_sync(0xffffffffu, xi, lbase | qp);

    float eu[8];
    {
        float d0 = xr - gS[0];
        float delta = gS[1] - gS[0];
        float e0 = __expf(-d0 * d0);
        float s  = __expf(2.f * delta * d0);
        eu[0] = e0;
        float sp = s;
#pragma unroll
        for (int u = 1; u < 8; u++) {
            eu[u] = e0 * sp * sKu[u];
            sp *= s;
        }
    }
    float gv0 = gS[8 + 2 * q], gv1 = gS[8 + 2 * q + 1];
    float ev0[4], ev1[4];
#pragma unroll
    for (int qp = 0; qp < 4; qp++) {
        float d0 = xiq[qp] - gv0; ev0[qp] = __expf(-d0 * d0);
        float d1 = xiq[qp] - gv1; ev1[qp] = __expf(-d1 * d1);
    }
#pragma unroll
    for (int qp = 0; qp < 4; qp++) {
#pragma unroll
        for (int u = 0; u < 8; u++) {
            float es = __shfl_sync(0xffffffffu, eu[u], lbase | qp);
            ph[qp][u] = pack_h2(es * ev0[qp], es * ev1[qp]);
        }
    }
}

__device__ __forceinline__ void build_A_silu(uint32_t ph[4][8],
                                             const float* x, int row_base,
                                             int i0, int gr, int q) {
#pragma unroll
    for (int qp = 0; qp < 4; qp++) {
        const float* xq = x + (size_t)(row_base + qp * 8 + gr) * (IN * DN) + i0 * 2;
#pragma unroll
        for (int ks = 0; ks < 2; ks++) {
            float2 p0 = *(const float2*)(xq + ks * 16 + 2 * q);
            float2 p1 = *(const float2*)(xq + ks * 16 + 8 + 2 * q);
            float s00 = p0.x / (1.f + __expf(-p0.x));
            float s01 = p0.y / (1.f + __expf(-p0.y));
            float s10 = p1.x / (1.f + __expf(-p1.x));
            float s11 = p1.y / (1.f + __expf(-p1.y));
            ph[qp][2 * ks]     = pack_h2(s00, s01);
            ph[qp][2 * ks + 1] = pack_h2(s10, s11);
        }
#pragma unroll
        for (int u = 4; u < 8; u++) ph[qp][u] = 0u;
    }
}

// ---------------------------------------------------------------------------
// Tensor-core split-K GEMM via mma.sync (fp16 single-pass), A IN REGISTERS,
// B through a 3-stage cp.async ring (CP_WAIT(1): iter-top wait is free).
// grid (16, 2, SPLIT) = 256 CTAs, 2 CTAs/SM. CTA 128x128, warp tile 32x64.
// (R11-proven: 44.1 us measured.)
// ---------------------------------------------------------------------------
__global__ __launch_bounds__(256, 2)
void k_tc(const float* __restrict__ x, const float* __restrict__ grd) {
    extern __shared__ char smdyn[];
    __shared__ float gS[16];
    __shared__ float sKu[8];

    const int tid = threadIdx.x;
    const int wid = tid >> 5, lid = tid & 31;
    const int bm = blockIdx.x * 128;
    const int n0 = blockIdx.y * 128;
    const int sl = blockIdx.z;
    const int i0 = sl * IPS;

    const uint32_t sbase = smem_u32(smdyn);
    const int wm = wid >> 1, wn = wid & 1;
    const int R = wm * 32, C = wn * 64;
    const int gr = lid >> 2, q = lid & 3;
    const int r_own = R + q * 8 + gr;
    const float* xp_own = x + (size_t)(bm + r_own) * (IN * DN);

    float acc[2][8][4];
#pragma unroll
    for (int t = 0; t < 2; t++)
#pragma unroll
        for (int j = 0; j < 8; j++)
#pragma unroll
            for (int e = 0; e < 4; e++) acc[t][j][e] = 0.f;

    // ---- preamble: issue B(0), B(1); init gS + Ku ----
#pragma unroll
    for (int pre = 0; pre < 2; pre++) {
        const __half* sH = g_w + ((size_t)(i0 + pre) * NN + n0) * 64;
#pragma unroll
        for (int c = 0; c < 4; c++) {
            int ch = tid + c * 256;
            uint32_t dst = (uint32_t)((ch >> 3) * (RPAD * 2) + (ch & 7) * 16);
            CP_ASYNC16(sbase + B_OFF(pre) + dst, sH + ch * 8);
        }
        CP_COMMIT();
    }
    if (tid < 8) {
        gS[tid]     = grd[tid * 16];       // g[u] (real axis)
        gS[8 + tid] = grd[tid * 2 + 1];    // g[v] (imag axis)
    }
    __syncthreads();
    if (tid < 8) {
        float du = gS[tid] - gS[0];
        sKu[tid] = __expf(-du * du);
    }
    __syncthreads();

    uint32_t ph[4][8];
    build_A_rbf(ph, xp_own, i0, gS, sKu, lid, q);

    for (int ii = 0; ii <= IPS; ii++) {
        const uint32_t bufB = sbase + B_OFF(ii % 3);

        if (ii < IPS) CP_WAIT(1);          // B(ii) is the oldest group -> done
        else          CP_WAIT(0);          // last iter: drain all
        __syncthreads();                   // B(ii) visible; stage (ii+2)%3 reads done

        // ---- issue cp.async for B(ii+2) into stage (ii+2)%3 ----
        if (ii + 2 <= IPS) {
            const __half* sH;
            if (ii + 2 < IPS)
                sH = g_w + ((size_t)(i0 + ii + 2) * NN + n0) * 64;
            else
                sH = g_s + ((size_t)sl * NN + n0) * 64;
            uint32_t nb = sbase + B_OFF((ii + 2) % 3);
#pragma unroll
            for (int c = 0; c < 4; c++) {
                int ch = tid + c * 256;
                uint32_t dst = (uint32_t)((ch >> 3) * (RPAD * 2) + (ch & 7) * 16);
                CP_ASYNC16(nb + dst, sH + ch * 8);
            }
            CP_COMMIT();
        }

        // ---- MMA over K=64: 4 k-steps, A from registers, B from smem ----
#pragma unroll
        for (int ks = 0; ks < 4; ks++) {
            uint32_t a0[4] = { ph[0][2 * ks], ph[1][2 * ks],
                               ph[0][2 * ks + 1], ph[1][2 * ks + 1] };
            uint32_t a1[4] = { ph[2][2 * ks], ph[3][2 * ks],
                               ph[2][2 * ks + 1], ph[3][2 * ks + 1] };
#pragma unroll
            for (int jj = 0; jj < 4; jj++) {
                int nrow = C + jj * 16 + ((lid >> 4) * 8) + (lid & 7);
                uint32_t cb = (uint32_t)(ks * 32 + ((lid >> 3) & 1) * 16);
                uint32_t bh[4];
                ldsm_x4(bh, bufB + (uint32_t)(nrow * (RPAD * 2)) + cb);
                mma_f16(acc[0][jj * 2],     a0, bh);
                mma_f16(acc[0][jj * 2 + 1], a0, bh + 2);
                mma_f16(acc[1][jj * 2],     a1, bh);
                mma_f16(acc[1][jj * 2 + 1], a1, bh + 2);
            }
        }

        // ---- build A-frags for next iter (overlaps HMMA drain) ----
        if (ii + 1 < IPS)
            build_A_rbf(ph, xp_own, i0 + ii + 1, gS, sKu, lid, q);
        else if (ii + 1 == IPS)
            build_A_silu(ph, x + (size_t)bm * (IN * DN), R, i0, gr, q);
    }

    // ---- epilogue: registers -> split-K partials ----
#pragma unroll
    for (int t = 0; t < 2; t++) {
#pragma unroll
        for (int j = 0; j < 8; j++) {
            int row = bm + R + t * 16 + (lid >> 2);
            int col = n0 + C + j * 8 + (lid & 3) * 2;
            *(float2*)&g_part[sl][row][col]     = make_float2(acc[t][j][0], acc[t][j][1]);
            *(float2*)&g_part[sl][row + 8][col] = make_float2(acc[t][j][2], acc[t][j][3]);
        }
    }
}

// ---------------------------------------------------------------------------
// Combine: streaming partial-sum + per-CTA BN stats. grid 128 x 256,
// 4 float4 per thread for 32-deep MLP.
// ---------------------------------------------------------------------------
__global__ __launch_bounds__(256)
void k_combine() {
    __shared__ float rs[256], rq[256], rs1[256], rq1[256];
    const int tid = threadIdx.x;
    const int i0 = blockIdx.x * 1024 + tid;    // float4 ids i0 + {0,256,512,768}

    float4 v[4];
#pragma unroll
    for (int g = 0; g < 4; g++)
        v[g] = ((const float4*)g_sbsum)[(i0 + g * 256) & 63];
    const float4* pp = (const float4*)g_part;
#pragma unroll
    for (int s = 0; s < SPLIT; s++) {
#pragma unroll
        for (int g = 0; g < 4; g++) {
            float4 p = pp[(size_t)s * 131072 + i0 + g * 256];
            v[g].x += p.x; v[g].y += p.y; v[g].z += p.z; v[g].w += p.w;
        }
    }
#pragma unroll
    for (int g = 0; g < 4; g++)
        ((float4*)g_pre)[i0 + g * 256] = v[g];

    float a0 = 0.f, a1 = 0.f, b0 = 0.f, b1 = 0.f;
#pragma unroll
    for (int g = 0; g < 4; g++) {
        a0 += v[g].x + v[g].z;
        a1 += v[g].y + v[g].w;
        b0 += v[g].x * v[g].x + v[g].z * v[g].z;
        b1 += v[g].y * v[g].y + v[g].w * v[g].w;
    }
    rs[tid] = a0; rs1[tid] = a1; rq[tid] = b0; rq1[tid] = b1;
    __syncthreads();
    for (int s = 128; s >= 1; s >>= 1) {
        if (tid < s) {
            rs[tid] += rs[tid + s];  rs1[tid] += rs1[tid + s];
            rq[tid] += rq[tid + s];  rq1[tid] += rq1[tid + s];
        }
        __syncthreads();
    }
    if (tid == 0) {
        g_bstat[blockIdx.x][0] = rs[0];
        g_bstat[blockIdx.x][1] = rs1[0];
        g_bstat[blockIdx.x][2] = rq[0];
        g_bstat[blockIdx.x][3] = rq1[0];
    }
}

// ---------------------------------------------------------------------------
// Norm: redundant bstat reduce per CTA (128 entries), then normalize slice.
// ---------------------------------------------------------------------------
__global__ __launch_bounds__(256)
void k_norm(const float* __restrict__ gamma, const float* __restrict__ beta,
            float* __restrict__ out) {
    __shared__ float r[4][128];
    __shared__ float st[4];
    const int tid = threadIdx.x;
    if (tid < 128) {
#pragma unroll
        for (int j = 0; j < 4; j++)
            r[j][tid] = g_bstat[tid][j];
    }
    __syncthreads();
    for (int s = 64; s >= 1; s >>= 1) {
        if (tid < s) {
#pragma unroll
            for (int j = 0; j < 4; j++) r[j][tid] += r[j][tid + s];
        }
        __syncthreads();
    }
    if (tid < 2) {
        const float Ninv = 1.f / (2048.f * 128.f);
        float mean = r[tid][0] * Ninv;
        float var  = r[2 + tid][0] * Ninv - mean * mean;
        float sc   = gamma[tid] * rsqrtf(var + 1e-5f);
        st[tid]     = sc;
        st[2 + tid] = beta[tid] - mean * sc;
    }
    __syncthreads();

    int idx = blockIdx.x * 256 + tid;
    float s0 = st[0], s1 = st[1], h0 = st[2], h1 = st[3];
    float4 v = ((const float4*)g_pre)[idx];
    v.x = v.x * s0 + h0;
    v.y = v.y * s1 + h1;
    v.z = v.z * s0 + h0;
    v.w = v.w * s1 + h1;
    ((float4*)out)[idx] = v;
}

// ---------------------------------------------------------------------------
extern "C" void kernel_launch(void* const* d_in, const int* in_sizes, int n_in,
                              void* d_out, int out_size) {
    const float* x     = (const float*)d_in[0];
    const float* w     = (const float*)d_in[1];
    const float* sw    = (const float*)d_in[2];
    const float* sb    = (const float*)d_in[3];
    const float* gamma = (const float*)d_in[4];
    const float* beta  = (const float*)d_in[5];
    const float* grd   = (const float*)d_in[6];
    const float* cay   = (const float*)d_in[7];
    float* out = (float*)d_out;

    static int once = 0;
    if (!once) {
        cudaFuncSetAttribute(k_tc, cudaFuncAttributeMaxDynamicSharedMemorySize, SMEM_TC);
        once = 1;
    }

    k_prep<<<2561, 256>>>(w, sw, sb, cay);               // 1 (merged preps)
    k_tc<<<dim3(16, 2, SPLIT), 256, SMEM_TC>>>(x, grd);  // 2
    k_combine<<<NCOMB, 256>>>();                         // 3
    k_norm<<<512, 256>>>(gamma, beta, out);              // 4
}